// round 4
// baseline (speedup 1.0000x reference)
#include <cuda_runtime.h>

// Problem constants (fixed by setup_inputs): B=512 rows, K=T=2048 bits.
#define BB 512
#define TT 2048
#define L 64               // BCJR chunk length
#define NC (TT / L)        // 32 chunks
#define W 80               // warmup (path-merge) window, multiple of 16
#define NEGF (-1e4f)
#define BT 64              // k_bcjr block size (threads = b values)
// encoder chunking
#define ECH 64
#define ENC (TT / ECH)     // 32 encoder chunks

// ---------------- scratch (static device arrays; no allocations) -------------
// All [T][B] column-major: warp lanes = consecutive b -> coalesced.
// G.x = A' = y_sys + La/2 (note 0.5*Lc == 1), G.y = P' = y_par.
__device__ float2 g_G1[TT * BB];   // decoder-1 branch inputs
__device__ float2 g_G2[TT * BB];   // decoder-2 branch inputs
__device__ float  g_h1 [TT * BB];  // y1  (static systematic, col-major)
__device__ float  g_h1i[TT * BB];  // y1 interleaved (static)
__device__ float  g_n2c[TT * BB];  // n2 col-major
__device__ float  g_n3c[TT * BB];  // n3 col-major
__device__ float  g_L2 [TT * BB];  // decoder-2 full LLR
__device__ unsigned char g_xc[TT * BB];  // bits col-major
__device__ int    g_inv[TT];       // inverse interleaver
__device__ unsigned char g_dc[2 * ENC * BB];  // encoder chunk offsets
__device__ unsigned char g_ss[2 * ENC * BB];  // encoder chunk start states

// ---------------- init ------------------------------------------------------
__global__ void k_inv(const int* __restrict__ il) {
    int k = blockIdx.x * blockDim.x + threadIdx.x;
    if (k < TT) g_inv[il[k]] = k;
}

// ---------------- transpose inputs to [T][B] ---------------------------------
__global__ void k_tp(const int* __restrict__ x, const float* __restrict__ n1,
                     const float* __restrict__ n2, const float* __restrict__ n3) {
    __shared__ int   tx_[32][33];
    __shared__ float t1_[32][33];
    __shared__ float t2_[32][33];
    __shared__ float t3_[32][33];
    int t0 = blockIdx.x * 32, b0 = blockIdx.y * 32;
    int tx = threadIdx.x, ty = threadIdx.y;
    int src = (b0 + ty) * TT + t0 + tx;          // coalesced along t
    tx_[ty][tx] = x[src];
    t1_[ty][tx] = n1[src];
    t2_[ty][tx] = n2[src];
    t3_[ty][tx] = n3[src];
    __syncthreads();
    int dst = (t0 + ty) * BB + b0 + tx;          // coalesced along b
    int xv = tx_[tx][ty];
    g_xc [dst] = (unsigned char)xv;
    g_h1 [dst] = 2.f * (float)xv - 1.f + t1_[tx][ty];   // y1 = c1 + n1
    g_n2c[dst] = t2_[tx][ty];
    g_n3c[dst] = t3_[tx][ty];
}

// ---------------- chunk-parallel RSC encode ----------------------------------
// RSC (7,5): par = u ^ s1 ; s1' = u ^ s1 ^ s2 ; s2' = s1.  State map over GF(2)
// is affine: s_{t+L} = F^L s_t + d_chunk, with F = [[1,1],[1,0]], F^3 = I, so
// F^64 = F.  Phase 1: d_chunk from zero start.  Phase 2: compose (32 steps,
// loads prefetched).  Phase 3: emit parities from exact start states.
__global__ void k_enc1(const int* __restrict__ il) {
    int tid = blockIdx.x * blockDim.x + threadIdx.x;
    if (tid >= 2 * ENC * BB) return;
    int b = tid & (BB - 1);
    int c = (tid >> 9) & (ENC - 1);
    int e = tid >> 14;
    int s1 = 0, s2 = 0;
    int base = c * ECH;
    for (int k = 0; k < ECH; k++) {
        int t = base + k;
        int row = e ? il[t] : t;                 // il[t] warp-uniform -> coalesced
        int u = (int)g_xc[row * BB + b];
        int ns1 = u ^ s1 ^ s2; s2 = s1; s1 = ns1;
    }
    g_dc[tid] = (unsigned char)((s1 << 1) | s2);
}

__global__ void k_enc2() {
    int tid = blockIdx.x * blockDim.x + threadIdx.x;
    if (tid >= 2 * BB) return;
    int b = tid & (BB - 1);
    int e = tid >> 9;
    unsigned char d[ENC];                        // prefetch: 32 independent loads
    #pragma unroll
    for (int c = 0; c < ENC; c++) d[c] = g_dc[(e * ENC + c) * BB + b];
    int s1 = 0, s2 = 0;
    #pragma unroll
    for (int c = 0; c < ENC; c++) {
        g_ss[(e * ENC + c) * BB + b] = (unsigned char)((s1 << 1) | s2);
        int dd = (int)d[c];
        int ns1 = s1 ^ s2 ^ (dd >> 1);           // F * s + d   (F^64 = F)
        int ns2 = s1 ^ (dd & 1);
        s1 = ns1; s2 = ns2;
    }
}

__global__ void k_enc3(const int* __restrict__ il) {
    int tid = blockIdx.x * blockDim.x + threadIdx.x;
    if (tid >= 2 * ENC * BB) return;
    int b = tid & (BB - 1);
    int c = (tid >> 9) & (ENC - 1);
    int e = tid >> 14;
    int s = (int)g_ss[tid];
    int s1 = s >> 1, s2 = s & 1;
    int base = c * ECH;
    if (e == 0) {
        for (int k = 0; k < ECH; k++) {
            int t = base + k;
            int i = t * BB + b;
            int u = (int)g_xc[i];
            int p = u ^ s1;
            int ns1 = u ^ s1 ^ s2; s2 = s1; s1 = ns1;
            g_G1[i] = make_float2(g_h1[i], 2.f * (float)p - 1.f + g_n2c[i]);
        }
    } else {
        for (int k = 0; k < ECH; k++) {
            int t = base + k;
            int i = t * BB + b;
            int row = il[t];
            int u = (int)g_xc[row * BB + b];
            float h1i = g_h1[row * BB + b];
            g_h1i[i] = h1i;
            int p = u ^ s1;
            int ns1 = u ^ s1 ^ s2; s2 = s1; s1 = ns1;
            g_G2[i] = make_float2(h1i, 2.f * (float)p - 1.f + g_n3c[i]);
        }
    }
}

// ---------------- fused BCJR: forward + backward + LLR + scatter --------------
// Unnormalized max-plus recursion (shift-invariant; renorm every 16 steps;
// per-t constant offsets cancel in u1-u0).
//   g11 = A' + P', g10 = A' - P'
// forward:  n0=max(a0-g11,a1+g11) n1=max(a2+g10,a3-g10)
//           n2=max(a0+g11,a1-g11) n3=max(a2-g10,a3+g10)
// backward: n0=max(b0-g11,b2+g11) n1=max(b0+g11,b2-g11)
//           n2=max(b1+g10,b3-g10) n3=max(b1-g10,b3+g10)
#define FSTEP(T_) do { \
    float2 v = G[(T_) * BB + b]; \
    float g11 = v.x + v.y; float g10 = v.x - v.y; \
    float m0 = fmaxf(a0 - g11, a1 + g11); \
    float m1 = fmaxf(a2 + g10, a3 - g10); \
    float m2 = fmaxf(a0 + g11, a1 - g11); \
    float m3 = fmaxf(a2 - g10, a3 + g10); \
    a0 = m0; a1 = m1; a2 = m2; a3 = m3; } while (0)

#define BSTEP_G(g11, g10) do { \
    float m0 = fmaxf(b0 - (g11), b2 + (g11)); \
    float m1 = fmaxf(b0 + (g11), b2 - (g11)); \
    float m2 = fmaxf(b1 + (g10), b3 - (g10)); \
    float m3 = fmaxf(b1 - (g10), b3 + (g10)); \
    b0 = m0; b1 = m1; b2 = m2; b3 = m3; } while (0)

__global__ __launch_bounds__(BT) void k_bcjr(int dec, const int* __restrict__ il) {
    extern __shared__ float4 sA[];               // L * BT * 16B = 64 KB
    const float2* __restrict__ G = dec ? g_G2 : g_G1;
    int tid = threadIdx.x;
    int chunk = blockIdx.y;
    int b = (blockIdx.x << 6) + tid;
    int t0 = chunk * L, t1 = t0 + L;

    // ---- forward (warmup + chunk, alpha to shared) ----
    float a0, a1, a2, a3;
    int ws = t0 - W;
    if (ws <= 0) { ws = 0; a0 = 0.f; a1 = a2 = a3 = NEGF; }  // exact start
    else         { a0 = a1 = a2 = a3 = 0.f; }                // merged warmup
    for (int tb = ws; tb < t0; tb += 16) {
        #pragma unroll
        for (int k = 0; k < 16; k++) FSTEP(tb + k);
        a1 -= a0; a2 -= a0; a3 -= a0; a0 = 0.f;
    }
    for (int kb = 0; kb < L; kb += 16) {
        #pragma unroll
        for (int k = 0; k < 16; k++) {
            sA[(kb + k) * BT + tid] = make_float4(a0, a1, a2, a3); // pre-step alpha_t
            FSTEP(t0 + kb + k);
        }
        a1 -= a0; a2 -= a0; a3 -= a0; a0 = 0.f;
    }

    // ---- backward (warmup + chunk with LLR/extrinsic) ----
    float b0 = 0.f, b1 = 0.f, b2 = 0.f, b3 = 0.f;            // uniform (exact at TT)
    int we = t1 + W; if (we > TT) we = TT;
    for (int tb = we; tb > t1; tb -= 16) {
        #pragma unroll
        for (int k = 1; k <= 16; k++) {
            int t = tb - k;
            float2 v = G[t * BB + b];
            float g11 = v.x + v.y, g10 = v.x - v.y;
            BSTEP_G(g11, g10);
        }
        b1 -= b0; b2 -= b0; b3 -= b0; b0 = 0.f;
    }
    for (int kb = L - 16; kb >= 0; kb -= 16) {
        #pragma unroll
        for (int k = 15; k >= 0; k--) {
            int t = t0 + kb + k;
            float4 al = sA[(kb + k) * BT + tid];
            float2 v = G[t * BB + b];
            float g11 = v.x + v.y, g10 = v.x - v.y;
            // LLR with alpha_t, gamma_t, beta_{t+1}
            float u1 = fmaxf(fmaxf(al.x + g11 + b2, al.y + g11 + b0),
                             fmaxf(al.z + g10 + b1, al.w + g10 + b3));
            float u0 = fmaxf(fmaxf(al.x - g11 + b0, al.y - g11 + b2),
                             fmaxf(al.z - g10 + b3, al.w - g10 + b1));
            float llr = u1 - u0;
            float lh  = 0.5f * llr - v.x;        // 0.5*Le (Le = llr - 2*A')
            if (dec == 0) {
                int kd = g_inv[t];               // warp-uniform -> coalesced
                g_G2[kd * BB + b].x = lh + g_h1[t * BB + b];   // A2' interleaved
            } else {
                int kd = il[t];
                g_G1[kd * BB + b].x = lh + g_h1i[t * BB + b];  // A1' deinterleaved
                g_L2[t * BB + b] = llr;
            }
            BSTEP_G(g11, g10);
        }
        b1 -= b0; b2 -= b0; b3 -= b0; b0 = 0.f;
    }
}

// ---------------- final deinterleave + transpose to [B,K] ---------------------
__global__ void k_out(float* __restrict__ out) {
    __shared__ float tile[32][33];
    int j0 = blockIdx.x * 32, b0 = blockIdx.y * 32;
    int tx = threadIdx.x, ty = threadIdx.y;
    tile[ty][tx] = g_L2[g_inv[j0 + ty] * BB + b0 + tx];      // coalesced in b
    __syncthreads();
    out[(b0 + ty) * TT + j0 + tx] = tile[tx][ty];            // coalesced in j
}

// ---------------- launch ------------------------------------------------------
extern "C" void kernel_launch(void* const* d_in, const int* in_sizes, int n_in,
                              void* d_out, int out_size) {
    const int*   x  = (const int*)d_in[0];
    const float* n1 = (const float*)d_in[1];
    const float* n2 = (const float*)d_in[2];
    const float* n3 = (const float*)d_in[3];
    const int*   il = (const int*)d_in[4];
    float* out = (float*)d_out;

    const int smem = L * BT * (int)sizeof(float4);           // 64 KB dynamic
    cudaFuncSetAttribute(k_bcjr, cudaFuncAttributeMaxDynamicSharedMemorySize, smem);

    k_inv<<<(TT + 255) / 256, 256>>>(il);
    k_tp<<<dim3(TT / 32, BB / 32), dim3(32, 32)>>>(x, n1, n2, n3);
    k_enc1<<<(2 * ENC * BB + 255) / 256, 256>>>(il);
    k_enc2<<<32, 32>>>();
    k_enc3<<<(2 * ENC * BB + 255) / 256, 256>>>(il);

    for (int it = 0; it < 6; it++) {
        k_bcjr<<<dim3(BB / BT, NC), BT, smem>>>(0, il);
        k_bcjr<<<dim3(BB / BT, NC), BT, smem>>>(1, il);
    }
    k_out<<<dim3(TT / 32, BB / 32), dim3(32, 32)>>>(out);
}

// round 5
// speedup vs baseline: 3.3815x; 3.3815x over previous
#include <cuda_runtime.h>

// Problem constants (fixed by setup_inputs): B=512 rows, K=T=2048 bits.
#define BB 512
#define TT 2048
#define L 32               // BCJR chunk length
#define NC (TT / L)        // 64 chunks
#define W 80               // warmup (path-merge) window, multiple of 16
#define NEGF (-1e4f)
#define BT 64              // k_bcjr block size (threads = b values)
// encoder chunking
#define ECH 64
#define ENC (TT / ECH)     // 32 encoder chunks

// ---------------- scratch (static device arrays; no allocations) -------------
// All [T][B] column-major: warp lanes = consecutive b -> coalesced.
// G.x = A' = y_sys + La/2 (note 0.5*Lc == 1), G.y = P' = y_par.
__device__ float2 g_G1[TT * BB];   // decoder-1 branch inputs
__device__ float2 g_G2[TT * BB];   // decoder-2 branch inputs
__device__ float  g_h1 [TT * BB];  // y1  (static systematic, col-major)
__device__ float  g_h1i[TT * BB];  // y1 interleaved (static)
__device__ float  g_n2c[TT * BB];  // n2 col-major
__device__ float  g_n3c[TT * BB];  // n3 col-major
__device__ float  g_L2 [TT * BB];  // decoder-2 full LLR
__device__ unsigned char g_xc[TT * BB];  // bits col-major
__device__ int    g_inv[TT];       // inverse interleaver
__device__ unsigned char g_dc[2 * ENC * BB];  // encoder chunk offsets
__device__ unsigned char g_ss[2 * ENC * BB];  // encoder chunk start states

// ---------------- init ------------------------------------------------------
__global__ void k_inv(const int* __restrict__ il) {
    int k = blockIdx.x * blockDim.x + threadIdx.x;
    if (k < TT) g_inv[il[k]] = k;
}

// ---------------- transpose inputs to [T][B] ---------------------------------
__global__ void k_tp(const int* __restrict__ x, const float* __restrict__ n1,
                     const float* __restrict__ n2, const float* __restrict__ n3) {
    __shared__ int   tx_[32][33];
    __shared__ float t1_[32][33];
    __shared__ float t2_[32][33];
    __shared__ float t3_[32][33];
    int t0 = blockIdx.x * 32, b0 = blockIdx.y * 32;
    int tx = threadIdx.x, ty = threadIdx.y;
    int src = (b0 + ty) * TT + t0 + tx;          // coalesced along t
    tx_[ty][tx] = x[src];
    t1_[ty][tx] = n1[src];
    t2_[ty][tx] = n2[src];
    t3_[ty][tx] = n3[src];
    __syncthreads();
    int dst = (t0 + ty) * BB + b0 + tx;          // coalesced along b
    int xv = tx_[tx][ty];
    g_xc [dst] = (unsigned char)xv;
    g_h1 [dst] = 2.f * (float)xv - 1.f + t1_[tx][ty];   // y1 = c1 + n1
    g_n2c[dst] = t2_[tx][ty];
    g_n3c[dst] = t3_[tx][ty];
}

// ---------------- chunk-parallel RSC encode ----------------------------------
// RSC (7,5): par = u ^ s1 ; s1' = u ^ s1 ^ s2 ; s2' = s1.  State map over GF(2)
// is affine: s_{t+L} = F^L s_t + d_chunk, with F = [[1,1],[1,0]], F^3 = I, so
// F^64 = F.  Phase 1: d_chunk from zero start.  Phase 2: compose (prefetched).
// Phase 3: emit parities from exact start states.
__global__ void k_enc1(const int* __restrict__ il) {
    int tid = blockIdx.x * blockDim.x + threadIdx.x;
    if (tid >= 2 * ENC * BB) return;
    int b = tid & (BB - 1);
    int c = (tid >> 9) & (ENC - 1);
    int e = tid >> 14;
    int s1 = 0, s2 = 0;
    int base = c * ECH;
    for (int k = 0; k < ECH; k++) {
        int t = base + k;
        int row = e ? il[t] : t;                 // il[t] warp-uniform -> coalesced
        int u = (int)g_xc[row * BB + b];
        int ns1 = u ^ s1 ^ s2; s2 = s1; s1 = ns1;
    }
    g_dc[tid] = (unsigned char)((s1 << 1) | s2);
}

__global__ void k_enc2() {
    int tid = blockIdx.x * blockDim.x + threadIdx.x;
    if (tid >= 2 * BB) return;
    int b = tid & (BB - 1);
    int e = tid >> 9;
    unsigned char d[ENC];                        // prefetch: 32 independent loads
    #pragma unroll
    for (int c = 0; c < ENC; c++) d[c] = g_dc[(e * ENC + c) * BB + b];
    int s1 = 0, s2 = 0;
    #pragma unroll
    for (int c = 0; c < ENC; c++) {
        g_ss[(e * ENC + c) * BB + b] = (unsigned char)((s1 << 1) | s2);
        int dd = (int)d[c];
        int ns1 = s1 ^ s2 ^ (dd >> 1);           // F * s + d   (F^64 = F)
        int ns2 = s1 ^ (dd & 1);
        s1 = ns1; s2 = ns2;
    }
}

__global__ void k_enc3(const int* __restrict__ il) {
    int tid = blockIdx.x * blockDim.x + threadIdx.x;
    if (tid >= 2 * ENC * BB) return;
    int b = tid & (BB - 1);
    int c = (tid >> 9) & (ENC - 1);
    int e = tid >> 14;
    int s = (int)g_ss[tid];
    int s1 = s >> 1, s2 = s & 1;
    int base = c * ECH;
    if (e == 0) {
        for (int k = 0; k < ECH; k++) {
            int t = base + k;
            int i = t * BB + b;
            int u = (int)g_xc[i];
            int p = u ^ s1;
            int ns1 = u ^ s1 ^ s2; s2 = s1; s1 = ns1;
            g_G1[i] = make_float2(g_h1[i], 2.f * (float)p - 1.f + g_n2c[i]);
        }
    } else {
        for (int k = 0; k < ECH; k++) {
            int t = base + k;
            int i = t * BB + b;
            int row = il[t];
            int u = (int)g_xc[row * BB + b];
            float h1i = g_h1[row * BB + b];
            g_h1i[i] = h1i;
            int p = u ^ s1;
            int ns1 = u ^ s1 ^ s2; s2 = s1; s1 = ns1;
            g_G2[i] = make_float2(h1i, 2.f * (float)p - 1.f + g_n3c[i]);
        }
    }
}

// ---------------- fused BCJR: forward + backward + LLR + scatter --------------
// Unnormalized max-plus recursion (shift-invariant; renorm every 16 steps;
// per-t constant offsets cancel in u1-u0).
//   g11 = A' + P', g10 = A' - P'
#define FSTEPV(v) do { \
    float g11 = (v).x + (v).y; float g10 = (v).x - (v).y; \
    float m0 = fmaxf(a0 - g11, a1 + g11); \
    float m1 = fmaxf(a2 + g10, a3 - g10); \
    float m2 = fmaxf(a0 + g11, a1 - g11); \
    float m3 = fmaxf(a2 - g10, a3 + g10); \
    a0 = m0; a1 = m1; a2 = m2; a3 = m3; } while (0)

#define BSTEP_G(g11, g10) do { \
    float m0 = fmaxf(b0 - (g11), b2 + (g11)); \
    float m1 = fmaxf(b0 + (g11), b2 - (g11)); \
    float m2 = fmaxf(b1 + (g10), b3 - (g10)); \
    float m3 = fmaxf(b1 - (g10), b3 + (g10)); \
    b0 = m0; b1 = m1; b2 = m2; b3 = m3; } while (0)

__global__ __launch_bounds__(BT) void k_bcjr(int dec, const int* __restrict__ il) {
    __shared__ float4 sA[L * BT];                // 32 KB: chunk-local alpha
    const float2* __restrict__ G = dec ? g_G2 : g_G1;
    int tid = threadIdx.x;
    int chunk = blockIdx.y;
    int b = (blockIdx.x << 6) + tid;
    int t0 = chunk * L, t1 = t0 + L;

    // ---- forward (warmup + chunk, alpha to shared), MLP=16 prefetch ----
    float a0, a1, a2, a3;
    int ws = t0 - W;
    if (ws <= 0) { ws = 0; a0 = 0.f; a1 = a2 = a3 = NEGF; }  // exact start
    else         { a0 = a1 = a2 = a3 = 0.f; }                // merged warmup
    for (int tb = ws; tb < t0; tb += 16) {
        float2 v[16];
        #pragma unroll
        for (int k = 0; k < 16; k++) v[k] = G[(tb + k) * BB + b];
        #pragma unroll
        for (int k = 0; k < 16; k++) FSTEPV(v[k]);
        a1 -= a0; a2 -= a0; a3 -= a0; a0 = 0.f;
    }
    #pragma unroll
    for (int kb = 0; kb < L; kb += 16) {
        float2 v[16];
        #pragma unroll
        for (int k = 0; k < 16; k++) v[k] = G[(t0 + kb + k) * BB + b];
        #pragma unroll
        for (int k = 0; k < 16; k++) {
            sA[(kb + k) * BT + tid] = make_float4(a0, a1, a2, a3); // pre-step alpha_t
            FSTEPV(v[k]);
        }
        a1 -= a0; a2 -= a0; a3 -= a0; a0 = 0.f;
    }

    // ---- backward (warmup + chunk with LLR/extrinsic) ----
    float b0 = 0.f, b1 = 0.f, b2 = 0.f, b3 = 0.f;            // uniform (exact at TT)
    int we = t1 + W; if (we > TT) we = TT;
    for (int tb = we; tb > t1; tb -= 16) {
        float2 v[16];
        #pragma unroll
        for (int k = 0; k < 16; k++) v[k] = G[(tb - 16 + k) * BB + b];
        #pragma unroll
        for (int k = 15; k >= 0; k--) {
            float g11 = v[k].x + v[k].y, g10 = v[k].x - v[k].y;
            BSTEP_G(g11, g10);
        }
        b1 -= b0; b2 -= b0; b3 -= b0; b0 = 0.f;
    }
    #pragma unroll
    for (int kb = L - 16; kb >= 0; kb -= 16) {
        float2 v[16];
        int   kd[16];
        float hh[16];
        #pragma unroll
        for (int k = 0; k < 16; k++) v[k] = G[(t0 + kb + k) * BB + b];
        #pragma unroll
        for (int k = 0; k < 16; k++) kd[k] = dec ? il[t0 + kb + k] : g_inv[t0 + kb + k];
        #pragma unroll
        for (int k = 0; k < 16; k++)
            hh[k] = dec ? g_h1i[(t0 + kb + k) * BB + b] : g_h1[(t0 + kb + k) * BB + b];
        #pragma unroll
        for (int k = 15; k >= 0; k--) {
            float4 al = sA[(kb + k) * BT + tid];
            float g11 = v[k].x + v[k].y, g10 = v[k].x - v[k].y;
            // LLR with alpha_t, gamma_t, beta_{t+1}
            float u1 = fmaxf(fmaxf(al.x + g11 + b2, al.y + g11 + b0),
                             fmaxf(al.z + g10 + b1, al.w + g10 + b3));
            float u0 = fmaxf(fmaxf(al.x - g11 + b0, al.y - g11 + b2),
                             fmaxf(al.z - g10 + b3, al.w - g10 + b1));
            float llr = u1 - u0;
            float lh  = 0.5f * llr - v[k].x;     // 0.5*Le (Le = llr - 2*A')
            if (dec == 0) {
                g_G2[kd[k] * BB + b].x = lh + hh[k];   // A2' at interleaved pos
            } else {
                g_G1[kd[k] * BB + b].x = lh + hh[k];   // A1' deinterleaved
                g_L2[(t0 + kb + k) * BB + b] = llr;
            }
            BSTEP_G(g11, g10);
        }
        b1 -= b0; b2 -= b0; b3 -= b0; b0 = 0.f;
    }
}

// ---------------- final deinterleave + transpose to [B,K] ---------------------
__global__ void k_out(float* __restrict__ out) {
    __shared__ float tile[32][33];
    int j0 = blockIdx.x * 32, b0 = blockIdx.y * 32;
    int tx = threadIdx.x, ty = threadIdx.y;
    tile[ty][tx] = g_L2[g_inv[j0 + ty] * BB + b0 + tx];      // coalesced in b
    __syncthreads();
    out[(b0 + ty) * TT + j0 + tx] = tile[tx][ty];            // coalesced in j
}

// ---------------- launch ------------------------------------------------------
extern "C" void kernel_launch(void* const* d_in, const int* in_sizes, int n_in,
                              void* d_out, int out_size) {
    const int*   x  = (const int*)d_in[0];
    const float* n1 = (const float*)d_in[1];
    const float* n2 = (const float*)d_in[2];
    const float* n3 = (const float*)d_in[3];
    const int*   il = (const int*)d_in[4];
    float* out = (float*)d_out;

    k_inv<<<(TT + 255) / 256, 256>>>(il);
    k_tp<<<dim3(TT / 32, BB / 32), dim3(32, 32)>>>(x, n1, n2, n3);
    k_enc1<<<(2 * ENC * BB + 255) / 256, 256>>>(il);
    k_enc2<<<32, 32>>>();
    k_enc3<<<(2 * ENC * BB + 255) / 256, 256>>>(il);

    for (int it = 0; it < 6; it++) {
        k_bcjr<<<dim3(BB / BT, NC), BT>>>(0, il);
        k_bcjr<<<dim3(BB / BT, NC), BT>>>(1, il);
    }
    k_out<<<dim3(TT / 32, BB / 32), dim3(32, 32)>>>(out);
}

// round 9
// speedup vs baseline: 3.5769x; 1.0578x over previous
#include <cuda_runtime.h>

// Problem constants (fixed by setup_inputs): B=512 rows, K=T=2048 bits.
#define BB 512
#define TT 2048
#define L 32               // BCJR chunk length
#define NC (TT / L)        // 64 chunks
#define W 80               // warmup (path-merge) window, multiple of 16
#define NEGF (-1e4f)
#define BT 64              // k_bcjr block size (threads = b values)
// encoder chunking
#define ECH 64
#define ENC (TT / ECH)     // 32 encoder chunks

// ---------------- scratch (static device arrays; no allocations) -------------
// All [T][B] column-major: warp lanes = consecutive b -> coalesced.
// G.x = A' = y_sys + La/2 (note 0.5*Lc == 1), G.y = P' = y_par.
__device__ float2 g_G1[TT * BB];   // decoder-1 branch inputs
__device__ float2 g_G2[TT * BB];   // decoder-2 branch inputs
__device__ float  g_h1 [TT * BB];  // y1  (static systematic, col-major)
__device__ float  g_h1i[TT * BB];  // y1 interleaved (static)
__device__ float  g_n2c[TT * BB];  // n2 col-major
__device__ float  g_n3c[TT * BB];  // n3 col-major
__device__ float  g_L2 [TT * BB];  // decoder-2 full LLR
__device__ unsigned char g_xc[TT * BB];  // bits col-major
__device__ int    g_inv[TT];       // inverse interleaver
__device__ unsigned char g_dc[2 * BB * ENC];  // chunk offsets, [row][chunk]
__device__ unsigned char g_ss[2 * BB * ENC];  // chunk start states, [row][chunk]

// ---------------- init ------------------------------------------------------
__global__ void k_inv(const int* __restrict__ il) {
    int k = blockIdx.x * blockDim.x + threadIdx.x;
    if (k < TT) g_inv[il[k]] = k;
}

// ---------------- transpose inputs to [T][B] ---------------------------------
__global__ void k_tp(const int* __restrict__ x, const float* __restrict__ n1,
                     const float* __restrict__ n2, const float* __restrict__ n3) {
    __shared__ int   tx_[32][33];
    __shared__ float t1_[32][33];
    __shared__ float t2_[32][33];
    __shared__ float t3_[32][33];
    int t0 = blockIdx.x * 32, b0 = blockIdx.y * 32;
    int tx = threadIdx.x, ty = threadIdx.y;
    int src = (b0 + ty) * TT + t0 + tx;          // coalesced along t
    tx_[ty][tx] = x[src];
    t1_[ty][tx] = n1[src];
    t2_[ty][tx] = n2[src];
    t3_[ty][tx] = n3[src];
    __syncthreads();
    int dst = (t0 + ty) * BB + b0 + tx;          // coalesced along b
    int xv = tx_[tx][ty];
    g_xc [dst] = (unsigned char)xv;
    g_h1 [dst] = 2.f * (float)xv - 1.f + t1_[tx][ty];   // y1 = c1 + n1
    g_n2c[dst] = t2_[tx][ty];
    g_n3c[dst] = t3_[tx][ty];
}

// ---------------- chunk-parallel RSC encode ----------------------------------
// RSC (7,5): par = u ^ s1 ; s1' = u ^ s1 ^ s2 ; s2' = s1.  State map over GF(2)
// is affine: s_{t+ECH} = F^(ECH mod 3) s_t + d_chunk = F s_t + d (F^3 = I).
// Phase 1: d per chunk from zero start.  Phase 2: warp-scan compose of affine
// maps.  Phase 3: emit parities from exact start states.
__global__ void k_enc1(const int* __restrict__ il) {
    int tid = blockIdx.x * blockDim.x + threadIdx.x;
    if (tid >= 2 * ENC * BB) return;
    int b = tid & (BB - 1);
    int c = (tid >> 9) & (ENC - 1);
    int e = tid >> 14;
    int s1 = 0, s2 = 0;
    int base = c * ECH;
    for (int k = 0; k < ECH; k++) {
        int t = base + k;
        int row = e ? il[t] : t;                 // il[t] warp-uniform -> coalesced
        int u = (int)g_xc[row * BB + b];
        int ns1 = u ^ s1 ^ s2; s2 = s1; s1 = ns1;
    }
    g_dc[(e * BB + b) * ENC + c] = (unsigned char)((s1 << 1) | s2);
}

__device__ __forceinline__ int fapply(int m, int d) {   // F^m * d over GF(2)^2
    int d1 = d >> 1, d2 = d & 1;
    if (m == 1) return ((d1 ^ d2) << 1) | d1;
    if (m == 2) return (d2 << 1) | (d1 ^ d2);
    return d;
}

__global__ void k_enc2() {   // warp per (e,b): affine prefix scan over 32 chunks
    int tid = blockIdx.x * blockDim.x + threadIdx.x;
    int lane = tid & 31;
    int w = tid >> 5;                            // 0..1023
    int b = w & (BB - 1);
    int e = w >> 9;
    int d = (int)g_dc[(e * BB + b) * ENC + lane];   // coalesced
    int m = 1;                                   // each chunk map: s -> F s + d
    #pragma unroll
    for (int off = 1; off < 32; off <<= 1) {     // inclusive scan (hi = self)
        int dm = __shfl_up_sync(0xffffffffu, m, off);
        int dd = __shfl_up_sync(0xffffffffu, d, off);
        if (lane >= off) {
            d = fapply(m, dd) ^ d;               // F^{m_hi} d_lo + d_hi
            m = m + dm; if (m >= 3) m -= 3;
        }
    }
    int sx = __shfl_up_sync(0xffffffffu, d, 1);  // exclusive prefix, applied to 0
    int s = (lane == 0) ? 0 : sx;
    g_ss[(e * BB + b) * ENC + lane] = (unsigned char)s;
}

__global__ void k_enc3(const int* __restrict__ il) {
    int tid = blockIdx.x * blockDim.x + threadIdx.x;
    if (tid >= 2 * ENC * BB) return;
    int b = tid & (BB - 1);
    int c = (tid >> 9) & (ENC - 1);
    int e = tid >> 14;
    int s = (int)g_ss[(e * BB + b) * ENC + c];
    int s1 = s >> 1, s2 = s & 1;
    int base = c * ECH;
    if (e == 0) {
        for (int k = 0; k < ECH; k++) {
            int t = base + k;
            int i = t * BB + b;
            int u = (int)g_xc[i];
            int p = u ^ s1;
            int ns1 = u ^ s1 ^ s2; s2 = s1; s1 = ns1;
            g_G1[i] = make_float2(g_h1[i], 2.f * (float)p - 1.f + g_n2c[i]);
        }
    } else {
        for (int k = 0; k < ECH; k++) {
            int t = base + k;
            int i = t * BB + b;
            int row = il[t];
            int u = (int)g_xc[row * BB + b];
            float h1i = g_h1[row * BB + b];
            g_h1i[i] = h1i;
            int p = u ^ s1;
            int ns1 = u ^ s1 ^ s2; s2 = s1; s1 = ns1;
            g_G2[i] = make_float2(h1i, 2.f * (float)p - 1.f + g_n3c[i]);
        }
    }
}

// ---------------- fused BCJR: forward + backward + LLR + scatter --------------
// Unnormalized max-plus recursion (shift-invariant; renorm every 16 steps;
// per-t constant offsets cancel in u1-u0).   g11 = A'+P', g10 = A'-P'
#define FSTEPV(v) do { \
    float g11 = (v).x + (v).y; float g10 = (v).x - (v).y; \
    float m0 = fmaxf(a0 - g11, a1 + g11); \
    float m1 = fmaxf(a2 + g10, a3 - g10); \
    float m2 = fmaxf(a0 + g11, a1 - g11); \
    float m3 = fmaxf(a2 - g10, a3 + g10); \
    a0 = m0; a1 = m1; a2 = m2; a3 = m3; } while (0)

#define BSTEP_G(g11, g10) do { \
    float m0 = fmaxf(b0 - (g11), b2 + (g11)); \
    float m1 = fmaxf(b0 + (g11), b2 - (g11)); \
    float m2 = fmaxf(b1 + (g10), b3 - (g10)); \
    float m3 = fmaxf(b1 - (g10), b3 + (g10)); \
    b0 = m0; b1 = m1; b2 = m2; b3 = m3; } while (0)

template <int DEC>
__global__ __launch_bounds__(BT) void k_bcjr(const int* __restrict__ il) {
    __shared__ float4 sA[L * BT];                // 32 KB: chunk-local alpha
    const float2* __restrict__ G  = DEC ? g_G2  : g_G1;
    const float*  __restrict__ H  = DEC ? g_h1i : g_h1;
    float2* __restrict__ Gdst     = DEC ? g_G1  : g_G2;
    int tid = threadIdx.x;
    int chunk = blockIdx.y;
    int b = (blockIdx.x << 6) + tid;
    int t0 = chunk * L, t1 = t0 + L;

    // ================= forward: software-pipelined 16-batches =================
    float a0, a1, a2, a3;
    int ws = t0 - W;
    if (ws <= 0) { ws = 0; a0 = 0.f; a1 = a2 = a3 = NEGF; }  // exact start
    else         { a0 = a1 = a2 = a3 = 0.f; }                // merged warmup

    auto loadG = [&](float2 (&v)[16], int tb) {
        #pragma unroll
        for (int k = 0; k < 16; k++) v[k] = G[(tb + k) * BB + b];
    };
    auto fbatch = [&](float2 (&v)[16], int tb) {
        if (tb >= t0) {
            int kb = tb - t0;
            #pragma unroll
            for (int k = 0; k < 16; k++) {
                sA[(kb + k) * BT + tid] = make_float4(a0, a1, a2, a3); // alpha_t
                FSTEPV(v[k]);
            }
        } else {
            #pragma unroll
            for (int k = 0; k < 16; k++) FSTEPV(v[k]);
        }
        a1 -= a0; a2 -= a0; a3 -= a0; a0 = 0.f;              // renorm
    };

    {
        float2 va[16], vb[16];
        int tb = ws, tend = t1;
        loadG(va, tb);
        bool flip = false;
        while (tb < tend) {
            if (!flip) {
                if (tb + 16 < tend) loadG(vb, tb + 16);
                fbatch(va, tb);
            } else {
                if (tb + 16 < tend) loadG(va, tb + 16);
                fbatch(vb, tb);
            }
            flip = !flip; tb += 16;
        }
    }

    // ================= backward: software-pipelined 16-batches ================
    float b0 = 0.f, b1 = 0.f, b2 = 0.f, b3 = 0.f;            // uniform (exact @TT)
    int we = t1 + W; if (we > TT) we = TT;

    auto loadB = [&](float2 (&v)[16], float (&hh)[16], int (&kd)[16], int tbs) {
        #pragma unroll
        for (int k = 0; k < 16; k++) v[k] = G[(tbs + k) * BB + b];
        if (tbs < t1) {                                      // LLR batch extras
            #pragma unroll
            for (int k = 0; k < 16; k++) kd[k] = DEC ? il[tbs + k] : g_inv[tbs + k];
            #pragma unroll
            for (int k = 0; k < 16; k++) hh[k] = H[(tbs + k) * BB + b];
        }
    };
    auto bbatch = [&](float2 (&v)[16], float (&hh)[16], int (&kd)[16], int tbs) {
        if (tbs < t1) {
            int kb = tbs - t0;
            #pragma unroll
            for (int k = 15; k >= 0; k--) {
                float4 al = sA[(kb + k) * BT + tid];
                float g11 = v[k].x + v[k].y, g10 = v[k].x - v[k].y;
                // LLR with alpha_t, gamma_t, beta_{t+1}
                float u1 = fmaxf(fmaxf(al.x + g11 + b2, al.y + g11 + b0),
                                 fmaxf(al.z + g10 + b1, al.w + g10 + b3));
                float u0 = fmaxf(fmaxf(al.x - g11 + b0, al.y - g11 + b2),
                                 fmaxf(al.z - g10 + b3, al.w - g10 + b1));
                float llr = u1 - u0;
                float lh  = 0.5f * llr - v[k].x;             // 0.5*Le
                Gdst[kd[k] * BB + b].x = lh + hh[k];         // fused (de)interleave
                if (DEC) g_L2[(tbs + k) * BB + b] = llr;
                BSTEP_G(g11, g10);
            }
        } else {
            #pragma unroll
            for (int k = 15; k >= 0; k--) {
                float g11 = v[k].x + v[k].y, g10 = v[k].x - v[k].y;
                BSTEP_G(g11, g10);
            }
        }
        b1 -= b0; b2 -= b0; b3 -= b0; b0 = 0.f;              // renorm
    };

    {
        float2 va[16], vb[16];
        float  ha[16], hb[16];
        int    ka[16], kb_[16];
        int tbs = we - 16;
        loadB(va, ha, ka, tbs);
        bool flip = false;
        while (tbs >= t0) {
            if (!flip) {
                if (tbs - 16 >= t0) loadB(vb, hb, kb_, tbs - 16);
                bbatch(va, ha, ka, tbs);
            } else {
                if (tbs - 16 >= t0) loadB(va, ha, ka, tbs - 16);
                bbatch(vb, hb, kb_, tbs);
            }
            flip = !flip; tbs -= 16;
        }
    }
}

// ---------------- final deinterleave + transpose to [B,K] ---------------------
__global__ void k_out(float* __restrict__ out) {
    __shared__ float tile[32][33];
    int j0 = blockIdx.x * 32, b0 = blockIdx.y * 32;
    int tx = threadIdx.x, ty = threadIdx.y;
    tile[ty][tx] = g_L2[g_inv[j0 + ty] * BB + b0 + tx];      // coalesced in b
    __syncthreads();
    out[(b0 + ty) * TT + j0 + tx] = tile[tx][ty];            // coalesced in j
}

// ---------------- launch ------------------------------------------------------
extern "C" void kernel_launch(void* const* d_in, const int* in_sizes, int n_in,
                              void* d_out, int out_size) {
    const int*   x  = (const int*)d_in[0];
    const float* n1 = (const float*)d_in[1];
    const float* n2 = (const float*)d_in[2];
    const float* n3 = (const float*)d_in[3];
    const int*   il = (const int*)d_in[4];
    float* out = (float*)d_out;

    k_inv<<<(TT + 255) / 256, 256>>>(il);
    k_tp<<<dim3(TT / 32, BB / 32), dim3(32, 32)>>>(x, n1, n2, n3);
    k_enc1<<<(2 * ENC * BB + 255) / 256, 256>>>(il);
    k_enc2<<<(2 * BB * 32) / 256, 256>>>();
    k_enc3<<<(2 * ENC * BB + 255) / 256, 256>>>(il);

    for (int it = 0; it < 6; it++) {
        k_bcjr<0><<<dim3(BB / BT, NC), BT>>>(il);
        k_bcjr<1><<<dim3(BB / BT, NC), BT>>>(il);
    }
    k_out<<<dim3(TT / 32, BB / 32), dim3(32, 32)>>>(out);
}

// round 11
// speedup vs baseline: 3.9232x; 1.0968x over previous
#include <cuda_runtime.h>

// Problem constants (fixed by setup_inputs): B=512 rows, K=T=2048 bits.
#define BB 512
#define TT 2048
#define L 32               // BCJR chunk length
#define NC (TT / L)        // 64 chunks
#define W 80               // warmup (path-merge) window, multiple of 16
#define NEGF (-1e4f)
#define BT 64              // b-values per block (per role)
// encoder chunking
#define ECH 64
#define ENC (TT / ECH)     // 32 encoder chunks

// ---------------- scratch (static device arrays; no allocations) -------------
// All [T][B] column-major: warp lanes = consecutive b -> coalesced.
// G.x = A' = y_sys + La/2 (note 0.5*Lc == 1), G.y = P' = y_par.
__device__ float2 g_G1[TT * BB];   // decoder-1 branch inputs
__device__ float2 g_G2[TT * BB];   // decoder-2 branch inputs
__device__ float  g_h1 [TT * BB];  // y1  (static systematic, col-major)
__device__ float  g_h1i[TT * BB];  // y1 interleaved (static)
__device__ float  g_n2c[TT * BB];  // n2 col-major
__device__ float  g_n3c[TT * BB];  // n3 col-major
__device__ float  g_L2 [TT * BB];  // decoder-2 full LLR
__device__ unsigned char g_xc[TT * BB];  // bits col-major
__device__ int    g_inv[TT];       // inverse interleaver
__device__ unsigned char g_dc[2 * BB * ENC];  // chunk offsets, [row][chunk]
__device__ unsigned char g_ss[2 * BB * ENC];  // chunk start states, [row][chunk]

// ---------------- transpose inputs to [T][B] (+ fused inverse interleaver) ---
__global__ void k_tp(const int* __restrict__ x, const float* __restrict__ n1,
                     const float* __restrict__ n2, const float* __restrict__ n3,
                     const int* __restrict__ il) {
    __shared__ int   tx_[32][33];
    __shared__ float t1_[32][33];
    __shared__ float t2_[32][33];
    __shared__ float t3_[32][33];
    int t0 = blockIdx.x * 32, b0 = blockIdx.y * 32;
    int tx = threadIdx.x, ty = threadIdx.y;
    if (blockIdx.y == 0 && ty == 0) {            // fused k_inv
        int t = t0 + tx;
        g_inv[il[t]] = t;
    }
    int src = (b0 + ty) * TT + t0 + tx;          // coalesced along t
    tx_[ty][tx] = x[src];
    t1_[ty][tx] = n1[src];
    t2_[ty][tx] = n2[src];
    t3_[ty][tx] = n3[src];
    __syncthreads();
    int dst = (t0 + ty) * BB + b0 + tx;          // coalesced along b
    int xv = tx_[tx][ty];
    g_xc [dst] = (unsigned char)xv;
    g_h1 [dst] = 2.f * (float)xv - 1.f + t1_[tx][ty];   // y1 = c1 + n1
    g_n2c[dst] = t2_[tx][ty];
    g_n3c[dst] = t3_[tx][ty];
}

// ---------------- chunk-parallel RSC encode ----------------------------------
// RSC (7,5): par = u ^ s1 ; s1' = u ^ s1 ^ s2 ; s2' = s1.  State map over GF(2)
// is affine: s_{t+ECH} = F^(ECH mod 3) s_t + d_chunk = F s_t + d (F^3 = I).
__global__ void k_enc1(const int* __restrict__ il) {
    int tid = blockIdx.x * blockDim.x + threadIdx.x;
    if (tid >= 2 * ENC * BB) return;
    int b = tid & (BB - 1);
    int c = (tid >> 9) & (ENC - 1);
    int e = tid >> 14;
    int s1 = 0, s2 = 0;
    int base = c * ECH;
    for (int k = 0; k < ECH; k++) {
        int t = base + k;
        int row = e ? il[t] : t;                 // il[t] warp-uniform -> coalesced
        int u = (int)g_xc[row * BB + b];
        int ns1 = u ^ s1 ^ s2; s2 = s1; s1 = ns1;
    }
    g_dc[(e * BB + b) * ENC + c] = (unsigned char)((s1 << 1) | s2);
}

__device__ __forceinline__ int fapply(int m, int d) {   // F^m * d over GF(2)^2
    int d1 = d >> 1, d2 = d & 1;
    if (m == 1) return ((d1 ^ d2) << 1) | d1;
    if (m == 2) return (d2 << 1) | (d1 ^ d2);
    return d;
}

__global__ void k_enc2() {   // warp per (e,b): affine prefix scan over 32 chunks
    int tid = blockIdx.x * blockDim.x + threadIdx.x;
    int lane = tid & 31;
    int w = tid >> 5;                            // 0..1023
    int b = w & (BB - 1);
    int e = w >> 9;
    int d = (int)g_dc[(e * BB + b) * ENC + lane];   // coalesced
    int m = 1;                                   // each chunk map: s -> F s + d
    #pragma unroll
    for (int off = 1; off < 32; off <<= 1) {     // inclusive scan (hi = self)
        int dm = __shfl_up_sync(0xffffffffu, m, off);
        int dd = __shfl_up_sync(0xffffffffu, d, off);
        if (lane >= off) {
            d = fapply(m, dd) ^ d;               // F^{m_hi} d_lo + d_hi
            m = m + dm; if (m >= 3) m -= 3;
        }
    }
    int sx = __shfl_up_sync(0xffffffffu, d, 1);  // exclusive prefix, applied to 0
    int s = (lane == 0) ? 0 : sx;
    g_ss[(e * BB + b) * ENC + lane] = (unsigned char)s;
}

__global__ void k_enc3(const int* __restrict__ il) {
    int tid = blockIdx.x * blockDim.x + threadIdx.x;
    if (tid >= 2 * ENC * BB) return;
    int b = tid & (BB - 1);
    int c = (tid >> 9) & (ENC - 1);
    int e = tid >> 14;
    int s = (int)g_ss[(e * BB + b) * ENC + c];
    int s1 = s >> 1, s2 = s & 1;
    int base = c * ECH;
    if (e == 0) {
        for (int k = 0; k < ECH; k++) {
            int t = base + k;
            int i = t * BB + b;
            int u = (int)g_xc[i];
            int p = u ^ s1;
            int ns1 = u ^ s1 ^ s2; s2 = s1; s1 = ns1;
            g_G1[i] = make_float2(g_h1[i], 2.f * (float)p - 1.f + g_n2c[i]);
        }
    } else {
        for (int k = 0; k < ECH; k++) {
            int t = base + k;
            int i = t * BB + b;
            int row = il[t];
            int u = (int)g_xc[row * BB + b];
            float h1i = g_h1[row * BB + b];
            g_h1i[i] = h1i;
            int p = u ^ s1;
            int ns1 = u ^ s1 ^ s2; s2 = s1; s1 = ns1;
            g_G2[i] = make_float2(h1i, 2.f * (float)p - 1.f + g_n3c[i]);
        }
    }
}

// ---------------- fused BCJR: concurrent fwd/bwd halves -----------------------
// Unnormalized max-plus recursion (shift-invariant; renorm every 16 steps;
// per-t constant offsets cancel in u1-u0).   g11 = A'+P', g10 = A'-P'
// Block = 128 threads: role 0 (tid<64) forward (warmup + alpha->smem);
// role 1 (tid>=64) backward warmup concurrently; sync; role 1 does LLR.
#define FSTEPV(v) do { \
    float g11 = (v).x + (v).y; float g10 = (v).x - (v).y; \
    float m0 = fmaxf(a0 - g11, a1 + g11); \
    float m1 = fmaxf(a2 + g10, a3 - g10); \
    float m2 = fmaxf(a0 + g11, a1 - g11); \
    float m3 = fmaxf(a2 - g10, a3 + g10); \
    a0 = m0; a1 = m1; a2 = m2; a3 = m3; } while (0)

#define BSTEP_G(g11, g10) do { \
    float m0 = fmaxf(b0 - (g11), b2 + (g11)); \
    float m1 = fmaxf(b0 + (g11), b2 - (g11)); \
    float m2 = fmaxf(b1 + (g10), b3 - (g10)); \
    float m3 = fmaxf(b1 - (g10), b3 + (g10)); \
    b0 = m0; b1 = m1; b2 = m2; b3 = m3; } while (0)

template <int DEC>
__global__ __launch_bounds__(2 * BT, 4) void k_bcjr(const int* __restrict__ il) {
    __shared__ float4 sA[L * BT];                // 32 KB: chunk-local alpha
    const float2* __restrict__ G  = DEC ? g_G2  : g_G1;
    const float*  __restrict__ H  = DEC ? g_h1i : g_h1;
    float2* __restrict__ Gdst     = DEC ? g_G1  : g_G2;
    int tid = threadIdx.x;
    int lane = tid & (BT - 1);
    int role = tid >> 6;
    int chunk = blockIdx.y;
    int b = (blockIdx.x << 6) + lane;
    int t0 = chunk * L, t1 = t0 + L;

    float b0 = 0.f, b1 = 0.f, b2 = 0.f, b3 = 0.f;            // beta (role 1)

    if (role == 0) {
        // ============ forward: software-pipelined 16-batches ============
        float a0, a1, a2, a3;
        int ws = t0 - W;
        if (ws <= 0) { ws = 0; a0 = 0.f; a1 = a2 = a3 = NEGF; }  // exact start
        else         { a0 = a1 = a2 = a3 = 0.f; }                // merged warmup

        auto loadG = [&](float2 (&v)[16], int tb) {
            #pragma unroll
            for (int k = 0; k < 16; k++) v[k] = G[(tb + k) * BB + b];
        };
        auto fbatch = [&](float2 (&v)[16], int tb) {
            if (tb >= t0) {
                int kb = tb - t0;
                #pragma unroll
                for (int k = 0; k < 16; k++) {
                    sA[(kb + k) * BT + lane] = make_float4(a0, a1, a2, a3);
                    FSTEPV(v[k]);
                }
            } else {
                #pragma unroll
                for (int k = 0; k < 16; k++) FSTEPV(v[k]);
            }
            a1 -= a0; a2 -= a0; a3 -= a0; a0 = 0.f;              // renorm
        };

        float2 va[16], vb[16];
        int tb = ws;
        loadG(va, tb);
        bool flip = false;
        while (tb < t1) {
            if (!flip) {
                if (tb + 16 < t1) loadG(vb, tb + 16);
                fbatch(va, tb);
            } else {
                if (tb + 16 < t1) loadG(va, tb + 16);
                fbatch(vb, tb);
            }
            flip = !flip; tb += 16;
        }
    } else {
        // ============ backward warmup: software-pipelined ============
        int we = t1 + W; if (we > TT) we = TT;                   // uniform @TT exact
        auto loadG = [&](float2 (&v)[16], int tbs) {
            #pragma unroll
            for (int k = 0; k < 16; k++) v[k] = G[(tbs + k) * BB + b];
        };
        auto wbatch = [&](float2 (&v)[16]) {
            #pragma unroll
            for (int k = 15; k >= 0; k--) {
                float g11 = v[k].x + v[k].y, g10 = v[k].x - v[k].y;
                BSTEP_G(g11, g10);
            }
            b1 -= b0; b2 -= b0; b3 -= b0; b0 = 0.f;              // renorm
        };
        float2 va[16], vb[16];
        int tbs = we - 16;
        if (tbs >= t1) {
            loadG(va, tbs);
            bool flip = false;
            while (tbs >= t1) {
                if (!flip) {
                    if (tbs - 16 >= t1) loadG(vb, tbs - 16);
                    wbatch(va);
                } else {
                    if (tbs - 16 >= t1) loadG(va, tbs - 16);
                    wbatch(vb);
                }
                flip = !flip; tbs -= 16;
            }
        }
    }

    __syncthreads();                             // alpha visible to role 1

    if (role == 1) {
        // ============ LLR phase: 2 batches of 16, descending ============
        #pragma unroll
        for (int half = 1; half >= 0; half--) {
            int tbs = t0 + half * 16;
            float2 v[16];
            float  hh[16];
            int    kd[16];
            #pragma unroll
            for (int k = 0; k < 16; k++) v[k] = G[(tbs + k) * BB + b];
            #pragma unroll
            for (int k = 0; k < 16; k++) kd[k] = DEC ? il[tbs + k] : g_inv[tbs + k];
            #pragma unroll
            for (int k = 0; k < 16; k++) hh[k] = H[(tbs + k) * BB + b];
            int kb = tbs - t0;
            #pragma unroll
            for (int k = 15; k >= 0; k--) {
                float4 al = sA[(kb + k) * BT + lane];
                float g11 = v[k].x + v[k].y, g10 = v[k].x - v[k].y;
                // LLR with alpha_t, gamma_t, beta_{t+1}
                float u1 = fmaxf(fmaxf(al.x + g11 + b2, al.y + g11 + b0),
                                 fmaxf(al.z + g10 + b1, al.w + g10 + b3));
                float u0 = fmaxf(fmaxf(al.x - g11 + b0, al.y - g11 + b2),
                                 fmaxf(al.z - g10 + b3, al.w - g10 + b1));
                float llr = u1 - u0;
                float lh  = 0.5f * llr - v[k].x;                 // 0.5*Le
                Gdst[kd[k] * BB + b].x = lh + hh[k];             // fused (de)ilv
                if (DEC) g_L2[(tbs + k) * BB + b] = llr;
                BSTEP_G(g11, g10);
            }
            b1 -= b0; b2 -= b0; b3 -= b0; b0 = 0.f;              // renorm
        }
    }
}

// ---------------- final deinterleave + transpose to [B,K] ---------------------
__global__ void k_out(float* __restrict__ out) {
    __shared__ float tile[32][33];
    int j0 = blockIdx.x * 32, b0 = blockIdx.y * 32;
    int tx = threadIdx.x, ty = threadIdx.y;
    tile[ty][tx] = g_L2[g_inv[j0 + ty] * BB + b0 + tx];      // coalesced in b
    __syncthreads();
    out[(b0 + ty) * TT + j0 + tx] = tile[tx][ty];            // coalesced in j
}

// ---------------- launch ------------------------------------------------------
extern "C" void kernel_launch(void* const* d_in, const int* in_sizes, int n_in,
                              void* d_out, int out_size) {
    const int*   x  = (const int*)d_in[0];
    const float* n1 = (const float*)d_in[1];
    const float* n2 = (const float*)d_in[2];
    const float* n3 = (const float*)d_in[3];
    const int*   il = (const int*)d_in[4];
    float* out = (float*)d_out;

    k_tp<<<dim3(TT / 32, BB / 32), dim3(32, 32)>>>(x, n1, n2, n3, il);
    k_enc1<<<(2 * ENC * BB + 255) / 256, 256>>>(il);
    k_enc2<<<(2 * BB * 32) / 256, 256>>>();
    k_enc3<<<(2 * ENC * BB + 255) / 256, 256>>>(il);

    for (int it = 0; it < 6; it++) {
        k_bcjr<0><<<dim3(BB / BT, NC), 2 * BT>>>(il);
        k_bcjr<1><<<dim3(BB / BT, NC), 2 * BT>>>(il);
    }
    k_out<<<dim3(TT / 32, BB / 32), dim3(32, 32)>>>(out);
}

// round 12
// speedup vs baseline: 4.7086x; 1.2002x over previous
#include <cuda_runtime.h>

// Problem constants (fixed by setup_inputs): B=512 rows, K=T=2048 bits.
#define BB 512
#define TT 2048
#define L 32               // BCJR chunk length
#define NC (TT / L)        // 64 chunks
#define W 80               // warmup (path-merge) window, multiple of 16
#define NEGF (-1e4f)
#define BT 64              // b-values per block (per role)
// encoder chunking
#define ECH 64
#define ENC (TT / ECH)     // 32 encoder chunks

// ---------------- scratch (static device arrays; no allocations) -------------
// All [T][B] column-major: warp lanes = consecutive b -> coalesced.
// G.x = A' = y_sys + La/2 (note 0.5*Lc == 1), G.y = P' = y_par.
__device__ float2 g_G1[TT * BB];   // decoder-1 branch inputs
__device__ float2 g_G2[TT * BB];   // decoder-2 branch inputs
__device__ float  g_h1 [TT * BB];  // y1  (static systematic, col-major)
__device__ float  g_h1i[TT * BB];  // y1 interleaved (static)
__device__ float  g_n2c[TT * BB];  // n2 col-major
__device__ float  g_n3c[TT * BB];  // n3 col-major
__device__ float  g_L2 [TT * BB];  // decoder-2 full LLR
__device__ unsigned char g_xc[TT * BB];  // bits col-major
__device__ int    g_inv[TT];       // inverse interleaver
__device__ unsigned char g_dc[2 * BB * ENC];  // chunk offsets, [row][chunk]
__device__ unsigned char g_ss[2 * BB * ENC];  // chunk start states, [row][chunk]

// ---------------- transpose inputs to [T][B] (+ fused inverse interleaver) ---
__global__ void k_tp(const int* __restrict__ x, const float* __restrict__ n1,
                     const float* __restrict__ n2, const float* __restrict__ n3,
                     const int* __restrict__ il) {
    __shared__ int   tx_[32][33];
    __shared__ float t1_[32][33];
    __shared__ float t2_[32][33];
    __shared__ float t3_[32][33];
    int t0 = blockIdx.x * 32, b0 = blockIdx.y * 32;
    int tx = threadIdx.x, ty = threadIdx.y;
    if (blockIdx.y == 0 && ty == 0) {            // fused k_inv
        int t = t0 + tx;
        g_inv[il[t]] = t;
    }
    int src = (b0 + ty) * TT + t0 + tx;          // coalesced along t
    tx_[ty][tx] = x[src];
    t1_[ty][tx] = n1[src];
    t2_[ty][tx] = n2[src];
    t3_[ty][tx] = n3[src];
    __syncthreads();
    int dst = (t0 + ty) * BB + b0 + tx;          // coalesced along b
    int xv = tx_[tx][ty];
    g_xc [dst] = (unsigned char)xv;
    g_h1 [dst] = 2.f * (float)xv - 1.f + t1_[tx][ty];   // y1 = c1 + n1
    g_n2c[dst] = t2_[tx][ty];
    g_n3c[dst] = t3_[tx][ty];
}

// ---------------- chunk-parallel RSC encode ----------------------------------
// RSC (7,5): par = u ^ s1 ; s1' = u ^ s1 ^ s2 ; s2' = s1.  State map over GF(2)
// is affine: s_{t+ECH} = F^(ECH mod 3) s_t + d_chunk = F s_t + d (F^3 = I).
// Phase 1: d per chunk (MLP-16 prefetched).  Phase 2: warp-scan compose.
// Phase 3: emit parities from exact start states (MLP-16 prefetched).
__global__ void k_enc1(const int* __restrict__ il) {
    int tid = blockIdx.x * blockDim.x + threadIdx.x;
    if (tid >= 2 * ENC * BB) return;
    int b = tid & (BB - 1);
    int c = (tid >> 9) & (ENC - 1);
    int e = tid >> 14;
    int s1 = 0, s2 = 0;
    int base = c * ECH;
    for (int kb = 0; kb < ECH; kb += 16) {
        int u[16];
        #pragma unroll
        for (int k = 0; k < 16; k++) {
            int t = base + kb + k;
            int row = e ? il[t] : t;             // il[t] warp-uniform -> coalesced
            u[k] = (int)g_xc[row * BB + b];
        }
        #pragma unroll
        for (int k = 0; k < 16; k++) {
            int ns1 = u[k] ^ s1 ^ s2; s2 = s1; s1 = ns1;
        }
    }
    g_dc[(e * BB + b) * ENC + c] = (unsigned char)((s1 << 1) | s2);
}

__device__ __forceinline__ int fapply(int m, int d) {   // F^m * d over GF(2)^2
    int d1 = d >> 1, d2 = d & 1;
    if (m == 1) return ((d1 ^ d2) << 1) | d1;
    if (m == 2) return (d2 << 1) | (d1 ^ d2);
    return d;
}

__global__ void k_enc2() {   // warp per (e,b): affine prefix scan over 32 chunks
    int tid = blockIdx.x * blockDim.x + threadIdx.x;
    int lane = tid & 31;
    int w = tid >> 5;                            // 0..1023
    int b = w & (BB - 1);
    int e = w >> 9;
    int d = (int)g_dc[(e * BB + b) * ENC + lane];   // coalesced
    int m = 1;                                   // each chunk map: s -> F s + d
    #pragma unroll
    for (int off = 1; off < 32; off <<= 1) {     // inclusive scan (hi = self)
        int dm = __shfl_up_sync(0xffffffffu, m, off);
        int dd = __shfl_up_sync(0xffffffffu, d, off);
        if (lane >= off) {
            d = fapply(m, dd) ^ d;               // F^{m_hi} d_lo + d_hi
            m = m + dm; if (m >= 3) m -= 3;
        }
    }
    int sx = __shfl_up_sync(0xffffffffu, d, 1);  // exclusive prefix, applied to 0
    int s = (lane == 0) ? 0 : sx;
    g_ss[(e * BB + b) * ENC + lane] = (unsigned char)s;
}

__global__ void k_enc3(const int* __restrict__ il) {
    int tid = blockIdx.x * blockDim.x + threadIdx.x;
    if (tid >= 2 * ENC * BB) return;
    int b = tid & (BB - 1);
    int c = (tid >> 9) & (ENC - 1);
    int e = tid >> 14;
    int s = (int)g_ss[(e * BB + b) * ENC + c];
    int s1 = s >> 1, s2 = s & 1;
    int base = c * ECH;
    if (e == 0) {
        for (int kb = 0; kb < ECH; kb += 16) {
            int u[16]; float h[16], n[16];
            #pragma unroll
            for (int k = 0; k < 16; k++) {       // MLP=16 prefetch
                int i = (base + kb + k) * BB + b;
                u[k] = (int)g_xc[i]; h[k] = g_h1[i]; n[k] = g_n2c[i];
            }
            #pragma unroll
            for (int k = 0; k < 16; k++) {
                int i = (base + kb + k) * BB + b;
                int p = u[k] ^ s1;
                int ns1 = u[k] ^ s1 ^ s2; s2 = s1; s1 = ns1;
                g_G1[i] = make_float2(h[k], 2.f * (float)p - 1.f + n[k]);
            }
        }
    } else {
        for (int kb = 0; kb < ECH; kb += 16) {
            int u[16]; float h[16], n[16];
            #pragma unroll
            for (int k = 0; k < 16; k++) {       // MLP=16 prefetch (gathered rows)
                int t = base + kb + k;
                int row = il[t];                 // warp-uniform -> coalesced
                u[k] = (int)g_xc[row * BB + b];
                h[k] = g_h1[row * BB + b];
                n[k] = g_n3c[t * BB + b];
            }
            #pragma unroll
            for (int k = 0; k < 16; k++) {
                int i = (base + kb + k) * BB + b;
                g_h1i[i] = h[k];
                int p = u[k] ^ s1;
                int ns1 = u[k] ^ s1 ^ s2; s2 = s1; s1 = ns1;
                g_G2[i] = make_float2(h[k], 2.f * (float)p - 1.f + n[k]);
            }
        }
    }
}

// ---------------- fused BCJR: concurrent fwd/bwd halves -----------------------
// Unnormalized max-plus recursion (shift-invariant; renorm every 16 steps;
// per-t constant offsets cancel in u1-u0).   g11 = A'+P', g10 = A'-P'
// Block = 128 threads: role 0 (tid<64) forward (warmup + alpha->smem);
// role 1 (tid>=64) backward warmup concurrently; sync; role 1 does LLR.
#define FSTEPV(v) do { \
    float g11 = (v).x + (v).y; float g10 = (v).x - (v).y; \
    float m0 = fmaxf(a0 - g11, a1 + g11); \
    float m1 = fmaxf(a2 + g10, a3 - g10); \
    float m2 = fmaxf(a0 + g11, a1 - g11); \
    float m3 = fmaxf(a2 - g10, a3 + g10); \
    a0 = m0; a1 = m1; a2 = m2; a3 = m3; } while (0)

#define BSTEP_G(g11, g10) do { \
    float m0 = fmaxf(b0 - (g11), b2 + (g11)); \
    float m1 = fmaxf(b0 + (g11), b2 - (g11)); \
    float m2 = fmaxf(b1 + (g10), b3 - (g10)); \
    float m3 = fmaxf(b1 - (g10), b3 + (g10)); \
    b0 = m0; b1 = m1; b2 = m2; b3 = m3; } while (0)

template <int DEC>
__global__ __launch_bounds__(2 * BT, 4) void k_bcjr(const int* __restrict__ il) {
    __shared__ float4 sA[L * BT];                // 32 KB: chunk-local alpha
    const float2* __restrict__ G  = DEC ? g_G2  : g_G1;
    const float*  __restrict__ H  = DEC ? g_h1i : g_h1;
    float2* __restrict__ Gdst     = DEC ? g_G1  : g_G2;
    int tid = threadIdx.x;
    int lane = tid & (BT - 1);
    int role = tid >> 6;
    int chunk = blockIdx.y;
    int b = (blockIdx.x << 6) + lane;
    int t0 = chunk * L, t1 = t0 + L;

    float b0 = 0.f, b1 = 0.f, b2 = 0.f, b3 = 0.f;            // beta (role 1)

    if (role == 0) {
        // ============ forward: software-pipelined 16-batches ============
        float a0, a1, a2, a3;
        int ws = t0 - W;
        if (ws <= 0) { ws = 0; a0 = 0.f; a1 = a2 = a3 = NEGF; }  // exact start
        else         { a0 = a1 = a2 = a3 = 0.f; }                // merged warmup

        auto loadG = [&](float2 (&v)[16], int tb) {
            #pragma unroll
            for (int k = 0; k < 16; k++) v[k] = G[(tb + k) * BB + b];
        };
        auto fbatch = [&](float2 (&v)[16], int tb) {
            if (tb >= t0) {
                int kb = tb - t0;
                #pragma unroll
                for (int k = 0; k < 16; k++) {
                    sA[(kb + k) * BT + lane] = make_float4(a0, a1, a2, a3);
                    FSTEPV(v[k]);
                }
            } else {
                #pragma unroll
                for (int k = 0; k < 16; k++) FSTEPV(v[k]);
            }
            a1 -= a0; a2 -= a0; a3 -= a0; a0 = 0.f;              // renorm
        };

        float2 va[16], vb[16];
        int tb = ws;
        loadG(va, tb);
        bool flip = false;
        while (tb < t1) {
            if (!flip) {
                if (tb + 16 < t1) loadG(vb, tb + 16);
                fbatch(va, tb);
            } else {
                if (tb + 16 < t1) loadG(va, tb + 16);
                fbatch(vb, tb);
            }
            flip = !flip; tb += 16;
        }
    } else {
        // ============ backward warmup: software-pipelined ============
        int we = t1 + W; if (we > TT) we = TT;                   // uniform @TT exact
        auto loadG = [&](float2 (&v)[16], int tbs) {
            #pragma unroll
            for (int k = 0; k < 16; k++) v[k] = G[(tbs + k) * BB + b];
        };
        auto wbatch = [&](float2 (&v)[16]) {
            #pragma unroll
            for (int k = 15; k >= 0; k--) {
                float g11 = v[k].x + v[k].y, g10 = v[k].x - v[k].y;
                BSTEP_G(g11, g10);
            }
            b1 -= b0; b2 -= b0; b3 -= b0; b0 = 0.f;              // renorm
        };
        float2 va[16], vb[16];
        int tbs = we - 16;
        if (tbs >= t1) {
            loadG(va, tbs);
            bool flip = false;
            while (tbs >= t1) {
                if (!flip) {
                    if (tbs - 16 >= t1) loadG(vb, tbs - 16);
                    wbatch(va);
                } else {
                    if (tbs - 16 >= t1) loadG(va, tbs - 16);
                    wbatch(vb);
                }
                flip = !flip; tbs -= 16;
            }
        }
    }

    __syncthreads();                             // alpha visible to role 1

    if (role == 1) {
        // ============ LLR phase: 2 batches of 16, descending ============
        #pragma unroll
        for (int half = 1; half >= 0; half--) {
            int tbs = t0 + half * 16;
            float2 v[16];
            float  hh[16];
            int    kd[16];
            #pragma unroll
            for (int k = 0; k < 16; k++) v[k] = G[(tbs + k) * BB + b];
            #pragma unroll
            for (int k = 0; k < 16; k++) kd[k] = DEC ? il[tbs + k] : g_inv[tbs + k];
            #pragma unroll
            for (int k = 0; k < 16; k++) hh[k] = H[(tbs + k) * BB + b];
            int kb = tbs - t0;
            #pragma unroll
            for (int k = 15; k >= 0; k--) {
                float4 al = sA[(kb + k) * BT + lane];
                float g11 = v[k].x + v[k].y, g10 = v[k].x - v[k].y;
                // LLR with alpha_t, gamma_t, beta_{t+1}
                float u1 = fmaxf(fmaxf(al.x + g11 + b2, al.y + g11 + b0),
                                 fmaxf(al.z + g10 + b1, al.w + g10 + b3));
                float u0 = fmaxf(fmaxf(al.x - g11 + b0, al.y - g11 + b2),
                                 fmaxf(al.z - g10 + b3, al.w - g10 + b1));
                float llr = u1 - u0;
                float lh  = 0.5f * llr - v[k].x;                 // 0.5*Le
                Gdst[kd[k] * BB + b].x = lh + hh[k];             // fused (de)ilv
                if (DEC) g_L2[(tbs + k) * BB + b] = llr;
                BSTEP_G(g11, g10);
            }
            b1 -= b0; b2 -= b0; b3 -= b0; b0 = 0.f;              // renorm
        }
    }
}

// ---------------- final deinterleave + transpose to [B,K] ---------------------
__global__ void k_out(float* __restrict__ out) {
    __shared__ float tile[32][33];
    int j0 = blockIdx.x * 32, b0 = blockIdx.y * 32;
    int tx = threadIdx.x, ty = threadIdx.y;
    tile[ty][tx] = g_L2[g_inv[j0 + ty] * BB + b0 + tx];      // coalesced in b
    __syncthreads();
    out[(b0 + ty) * TT + j0 + tx] = tile[tx][ty];            // coalesced in j
}

// ---------------- launch ------------------------------------------------------
extern "C" void kernel_launch(void* const* d_in, const int* in_sizes, int n_in,
                              void* d_out, int out_size) {
    const int*   x  = (const int*)d_in[0];
    const float* n1 = (const float*)d_in[1];
    const float* n2 = (const float*)d_in[2];
    const float* n3 = (const float*)d_in[3];
    const int*   il = (const int*)d_in[4];
    float* out = (float*)d_out;

    k_tp<<<dim3(TT / 32, BB / 32), dim3(32, 32)>>>(x, n1, n2, n3, il);
    k_enc1<<<(2 * ENC * BB + 255) / 256, 256>>>(il);
    k_enc2<<<(2 * BB * 32) / 256, 256>>>();
    k_enc3<<<(2 * ENC * BB + 255) / 256, 256>>>(il);

    for (int it = 0; it < 6; it++) {
        k_bcjr<0><<<dim3(BB / BT, NC), 2 * BT>>>(il);
        k_bcjr<1><<<dim3(BB / BT, NC), 2 * BT>>>(il);
    }
    k_out<<<dim3(TT / 32, BB / 32), dim3(32, 32)>>>(out);
}